// round 12
// baseline (speedup 1.0000x reference)
#include <cuda_runtime.h>
#include <cuda_fp16.h>
#include <cstdint>

// Problem constants
#define BATCH   2
#define NPTS    2048
#define CIN     64
#define COUT    128
#define GRIDV   12
#define NVOX    (GRIDV*GRIDV*GRIDV)   // 1728
#define NOFF    27
#define NGRP    2                     // offset groups: [0,14) and [14,27)
#define TM      64                    // points per conv block
#define NTILE   (BATCH*NPTS/TM)       // 64 point tiles
#define NROWS   (BATCH*NVOX)          // 3456
#define ZROW    NROWS                 // dedicated zero row index
#define OUTN    (BATCH*NPTS*COUT)     // 524288

// Scratch (device globals; no allocation allowed)
__device__ float g_aggF[NROWS * CIN];
__device__ __align__(16) unsigned char g_aggH[(NROWS + 1) * 128];  // fp16 rows (+zero row)
// W per offset: 16KB = [n][128B row], fp16, SW128-PRE-SWIZZLED
__device__ __align__(1024) unsigned char g_Wn[NOFF * 16384];
// split-K partials
__device__ float g_part[NGRP * OUTN];

// ---------------------------------------------------------------------------
// Helpers
// ---------------------------------------------------------------------------
#define CP_ASYNC16(dst_u32, src_ptr) \
    asm volatile("cp.async.cg.shared.global [%0], [%1], 16;" :: "r"(dst_u32), "l"(src_ptr))
#define CP_ASYNC_COMMIT() asm volatile("cp.async.commit_group;" ::: "memory")
#define CP_ASYNC_WAIT2()  asm volatile("cp.async.wait_group 2;" ::: "memory")

#define MBAR_INIT(a, c) \
    asm volatile("mbarrier.init.shared.b64 [%0], %1;" :: "r"(a), "r"(c) : "memory")
#define MBAR_EXPECT_TX(a, b) \
    asm volatile("mbarrier.arrive.expect_tx.shared.b64 _, [%0], %1;" :: "r"(a), "r"(b) : "memory")
#define BULK_G2S(dst, src, bytes, mbar) \
    asm volatile("cp.async.bulk.shared::cluster.global.mbarrier::complete_tx::bytes [%0], [%1], %2, [%3];" \
                 :: "r"(dst), "l"(src), "r"(bytes), "r"(mbar) : "memory")

__device__ __forceinline__ void mbar_wait_parity(uint32_t mbar, uint32_t parity) {
    asm volatile(
        "{\n\t.reg .pred P;\n\t"
        "WL_%=:\n\t"
        "mbarrier.try_wait.parity.acquire.cta.shared::cta.b64 P, [%0], %1, 0x989680;\n\t"
        "@!P bra WL_%=;\n\t}"
        :: "r"(mbar), "r"(parity) : "memory");
}

__device__ __forceinline__ uint32_t smem_u32(const void* p) {
    uint32_t a;
    asm("{ .reg .u64 t; cvta.to.shared.u64 t, %1; cvt.u32.u64 %0, t; }" : "=r"(a) : "l"(p));
    return a;
}

__device__ __forceinline__ void ldsm_x4(uint32_t* r, uint32_t addr) {
    asm volatile("ldmatrix.sync.aligned.m8n8.x4.shared.b16 {%0,%1,%2,%3}, [%4];"
                 : "=r"(r[0]), "=r"(r[1]), "=r"(r[2]), "=r"(r[3]) : "r"(addr));
}

__device__ __forceinline__ void mma_f16(float* c, const uint32_t* a, uint32_t b0, uint32_t b1) {
    asm volatile(
        "mma.sync.aligned.m16n8k16.row.col.f32.f16.f16.f32 "
        "{%0,%1,%2,%3}, {%4,%5,%6,%7}, {%8,%9}, {%0,%1,%2,%3};"
        : "+f"(c[0]), "+f"(c[1]), "+f"(c[2]), "+f"(c[3])
        : "r"(a[0]), "r"(a[1]), "r"(a[2]), "r"(a[3]), "r"(b0), "r"(b1));
}

__device__ __forceinline__ uint32_t pack_h(float f0, float f1) {
    __half h0 = __float2half(f0), h1 = __float2half(f1);
    return ((uint32_t)__half_as_ushort(h1) << 16) | __half_as_ushort(h0);
}

// ---------------------------------------------------------------------------
// Kernel 1: zero aggF + pack W (fp16, SW128 pre-swizzled)
// ---------------------------------------------------------------------------
__global__ void prep_kernel(const float* __restrict__ weight) {
    int bid = blockIdx.x;
    if (bid < 216) {
        int t = bid * 256 + threadIdx.x;
        ((float4*)g_aggF)[t] = make_float4(0.f, 0.f, 0.f, 0.f);
    } else {
        int i = (bid - 216) * 256 + threadIdx.x;   // 0..110591
        int n  = i & 127;
        int k2 = (i >> 7) & 31;
        int o  = i >> 12;                          // 0..26
        float w0 = weight[(o * CIN + 2 * k2) * COUT + n];
        float w1 = weight[(o * CIN + 2 * k2 + 1) * COUT + n];
        // SW128 swizzle: chunk bits[6:4] ^= (n&7)
        uint32_t off = (uint32_t)n * 128 + (((uint32_t)k2 * 4) ^ (((uint32_t)n & 7) << 4));
        *(uint32_t*)(g_Wn + (size_t)o * 16384 + off) = pack_h(w0, w1);
    }
}

// ---------------------------------------------------------------------------
// Kernel 2: scatter-add features into per-voxel bins
// ---------------------------------------------------------------------------
__global__ void aggregate_kernel(const float* __restrict__ points,
                                 const float* __restrict__ feats) {
    int gid = blockIdx.x * blockDim.x + threadIdx.x;
    if (gid >= BATCH * NPTS * CIN) return;
    int c = gid & (CIN - 1);
    int p = gid >> 6;
    int b = p / NPTS;
    int vx = (int)points[p * 3 + 0];
    int vy = (int)points[p * 3 + 1];
    int vz = (int)points[p * 3 + 2];
    if ((unsigned)vx >= GRIDV || (unsigned)vy >= GRIDV || (unsigned)vz >= GRIDV) return;
    int lin = (vx * GRIDV + vy) * GRIDV + vz;
    atomicAdd(&g_aggF[(b * NVOX + lin) * CIN + c], feats[gid]);
}

// ---------------------------------------------------------------------------
// Kernel 3: convert aggF -> fp16 rows (once per voxel), plus zero row
// ---------------------------------------------------------------------------
__global__ void convert_kernel() {
    int gid = blockIdx.x * blockDim.x + threadIdx.x;
    if (gid >= (NROWS + 1) * 32) return;
    int row = gid >> 5;
    int c2  = gid & 31;
    uint32_t hp = 0;
    if (row < NROWS) {
        float2 v = *(const float2*)(g_aggF + (size_t)row * CIN + c2 * 2);
        hp = pack_h(v.x, v.y);
    }
    *(uint32_t*)(g_aggH + (size_t)row * 128 + c2 * 4) = hp;
}

// ---------------------------------------------------------------------------
// Kernel 4: fp16 1-pass mma conv, 3-deep ring pipeline.
// grid = NTILE*NGRP = 128 blocks, 256 thr, 1 CTA/SM.
// Block (tile, g): 64 points x 128 couts over offsets g=0:[0,14) g=1:[14,27).
// Warp (wm 0..3, wn 0..1): 16 rows x 64 couts. Partials to g_part[g].
// ---------------------------------------------------------------------------
#define NSTG   3
#define RSTR   144
#define WBUF   16384                   // per-offset W (fp16, swizzled)
#define ABUF   (TM * RSTR)             // 9216
#define SMO_W  0
#define SMO_A  (NSTG * WBUF)           // 49152
#define SMO_VOX (SMO_A + NSTG * ABUF)  // 76800
#define SMO_MBAR (SMO_VOX + 3 * TM * 4)  // 77568
#define SMEM_TOTAL (SMO_MBAR + 64)     // 77632

__global__ __launch_bounds__(256, 1)
void conv_mma_kernel(const float* __restrict__ points) {
    extern __shared__ __align__(1024) unsigned char smem[];
    int* svox = (int*)(smem + SMO_VOX);

    const int tid  = threadIdx.x;
    const int warp = tid >> 5;
    const int lane = tid & 31;
    const int wm   = warp >> 1;      // 0..3 : rows [wm*16, +16)
    const int wn   = warp & 1;       // 0..1 : couts [wn*64, +64)
    const int grp  = lane >> 2;      // 0..7
    const int tig  = lane & 3;       // 0..3

    const int g    = blockIdx.x & 1;         // offset group
    const int tile = blockIdx.x >> 1;        // point tile
    const int o0   = g ? 14 : 0;
    const int OE   = g ? 13 : 14;            // offsets in this group
    const int p0   = tile * TM;
    const int b    = p0 >> 11;               // / NPTS

    if (tid < TM) {
        int p = p0 + tid;
        svox[tid]          = (int)points[p * 3 + 0];
        svox[TM + tid]     = (int)points[p * 3 + 1];
        svox[2 * TM + tid] = (int)points[p * 3 + 2];
    }
    __syncthreads();

    const uint32_t sb = smem_u32(smem);

    if (tid == 0) {
        MBAR_INIT(sb + SMO_MBAR,      1);
        MBAR_INIT(sb + SMO_MBAR + 8,  1);
        MBAR_INIT(sb + SMO_MBAR + 16, 1);
    }
    __syncthreads();

    // ---- A staging: 2 cp.async per thread (row = tid>>2, quarter = tid&3) ----
    const int arow = tid >> 2;           // 0..63
    const int aq   = tid & 3;            // 0..3 -> bytes [aq*32, +32)
    const int avx = svox[arow], avy = svox[TM + arow], avz = svox[2 * TM + arow];

    auto issueA = [&](int o, int s) {
        int dx = o / 9 - 1, dy = (o / 3) % 3 - 1, dz = o % 3 - 1;
        int nx = avx + dx, ny = avy + dy, nz = avz + dz;
        int rowIdx = ZROW;
        if ((unsigned)nx < GRIDV && (unsigned)ny < GRIDV && (unsigned)nz < GRIDV)
            rowIdx = b * NVOX + (nx * GRIDV + ny) * GRIDV + nz;
        const unsigned char* srcH = g_aggH + (size_t)rowIdx * 128 + aq * 32;
        uint32_t dstH = sb + SMO_A + s * ABUF + arow * RSTR + aq * 32;
        CP_ASYNC16(dstH,      srcH);
        CP_ASYNC16(dstH + 16, srcH + 16);
    };
    auto issueW = [&](int o, int s) {
        if (tid == 0) {
            uint32_t mb = sb + SMO_MBAR + s * 8;
            MBAR_EXPECT_TX(mb, WBUF);
            BULK_G2S(sb + SMO_W + s * WBUF, g_Wn + (size_t)o * WBUF, WBUF, mb);
        }
    };

    float c[32];
    #pragma unroll
    for (int i = 0; i < 32; i++) c[i] = 0.f;

    // ---- prologue: stages 0,1 for offsets o0, o0+1 (one commit group each) ----
    issueW(o0, 0);
    issueA(o0, 0);
    CP_ASYNC_COMMIT();
    issueW(o0 + 1, 1);
    issueA(o0 + 1, 1);
    CP_ASYNC_COMMIT();

    // ---- ldmatrix lane addressing ----
    const uint32_t aAddrBase = sb + SMO_A
        + (uint32_t)(wm * 16 + ((lane >> 3) & 1) * 8 + (lane & 7)) * RSTR
        + ((lane >> 4) & 1) * 16;
    const int bc   = lane & 7;
    const uint32_t bXor = (uint32_t)bc << 4;
    const uint32_t bRow0 = sb + SMO_W
        + (uint32_t)(wn * 64 + ((lane >> 4) & 1) * 8 + bc) * 128;
    const uint32_t bKsel = ((lane >> 3) & 1) * 16;

    for (int i = 0; i < OE; i++) {
        const int s = i % 3;

        // prefetch offset i+2 into stage (i+2)%3 (always commit one group)
        if (i + 2 < OE) {
            int s2 = (i + 2) % 3;
            issueW(o0 + i + 2, s2);
            issueA(o0 + i + 2, s2);
        }
        CP_ASYNC_COMMIT();

        // wait for stage i data: W mbar (parity (i/3)&1) + own cp.async groups
        mbar_wait_parity(sb + SMO_MBAR + s * 8, (uint32_t)((i / 3) & 1));
        CP_ASYNC_WAIT2();
        __syncthreads();

        // ---- 1-pass mma over 4 k-steps ----
        const uint32_t aH = aAddrBase + (uint32_t)s * ABUF;
        const uint32_t bB = bRow0 + (uint32_t)s * WBUF;
        #pragma unroll
        for (int kk = 0; kk < 4; kk++) {
            const uint32_t kx = ((uint32_t)(kk * 32) + bKsel) ^ bXor;
            uint32_t ah[4];
            ldsm_x4(ah, aH + kk * 32);
            #pragma unroll
            for (int j = 0; j < 4; j++) {
                uint32_t bh[4];
                ldsm_x4(bh, bB + j * 2048 + kx);
                mma_f16(&c[(2 * j) * 4],     ah, bh[0], bh[1]);
                mma_f16(&c[(2 * j + 1) * 4], ah, bh[2], bh[3]);
            }
        }

        __syncthreads();   // all reads of stage s done before its re-arm/overwrite
    }

    // ---- epilogue: vectorized partial write ----
    float* pout = g_part + (size_t)g * OUTN;
    const int r0 = p0 + wm * 16 + grp;
    #pragma unroll
    for (int f = 0; f < 8; f++) {
        int col = wn * 64 + f * 8 + tig * 2;
        const float* cc = &c[f * 4];
        *(float2*)(pout + (size_t)r0 * COUT + col)       = make_float2(cc[0], cc[1]);
        *(float2*)(pout + (size_t)(r0 + 8) * COUT + col) = make_float2(cc[2], cc[3]);
    }
}

// ---------------------------------------------------------------------------
// Kernel 5: reduce partials + bias -> out
// ---------------------------------------------------------------------------
__global__ void reduce_kernel(const float* __restrict__ bias, float* __restrict__ out) {
    int i = blockIdx.x * blockDim.x + threadIdx.x;   // float4 index, < OUTN/4
    if (i >= OUTN / 4) return;
    float4 a = ((const float4*)g_part)[i];
    float4 bq = ((const float4*)(g_part + OUTN))[i];
    float4 bv = ((const float4*)bias)[i & 31];
    float4 r;
    r.x = a.x + bq.x + bv.x;
    r.y = a.y + bq.y + bv.y;
    r.z = a.z + bq.z + bv.z;
    r.w = a.w + bq.w + bv.w;
    ((float4*)out)[i] = r;
}

// ---------------------------------------------------------------------------
extern "C" void kernel_launch(void* const* d_in, const int* in_sizes, int n_in,
                              void* d_out, int out_size) {
    const float* points  = (const float*)d_in[0];   // (B, N, 3)
    const float* feats   = (const float*)d_in[1];   // (B, N, CIN)
    const float* weight  = (const float*)d_in[2];   // (3,3,3,CIN,COUT)
    const float* bias    = (const float*)d_in[3];   // (COUT)
    float* out = (float*)d_out;                     // (B, N, COUT)

    cudaFuncSetAttribute(conv_mma_kernel,
                         cudaFuncAttributeMaxDynamicSharedMemorySize, SMEM_TOTAL);

    // 1) zero agg scratch + pack W (fp16 swizzled)
    prep_kernel<<<648, 256>>>(weight);
    // 2) per-voxel feature aggregation (fp32 atomics)
    aggregate_kernel<<<(BATCH * NPTS * CIN + 255) / 256, 256>>>(points, feats);
    // 3) convert aggF to fp16 rows (+ zero row)
    convert_kernel<<<((NROWS + 1) * 32 + 255) / 256, 256>>>();
    // 4) fp16 1-pass conv, 3-deep ring pipeline -> partials
    conv_mma_kernel<<<NTILE * NGRP, 256, SMEM_TOTAL>>>(points);
    // 5) reduce partials + bias -> out
    reduce_kernel<<<(OUTN / 4 + 255) / 256, 256>>>(bias, out);
}

// round 13
// speedup vs baseline: 1.2206x; 1.2206x over previous
#include <cuda_runtime.h>
#include <cuda_fp16.h>
#include <cstdint>

// Problem constants
#define BATCH   2
#define NPTS    2048
#define CIN     64
#define COUT    128
#define GRIDV   12
#define NVOX    (GRIDV*GRIDV*GRIDV)   // 1728
#define NOFF    27
#define NGRP    2                     // offset groups: [0,14) and [14,27)
#define TM      64                    // points per conv block
#define NTILE   (BATCH*NPTS/TM)       // 64 point tiles
#define NROWS   (BATCH*NVOX)          // 3456
#define ZROW    NROWS                 // dedicated zero row index
#define OUTN    (BATCH*NPTS*COUT)     // 524288

// Scratch (device globals; no allocation allowed)
__device__ float g_aggF[NROWS * CIN];
__device__ __align__(16) unsigned char g_aggH[(NROWS + 1) * 128];  // fp16 rows (+zero row)
// W per offset: 16KB = [n][128B row], fp16, SW128-PRE-SWIZZLED
__device__ __align__(1024) unsigned char g_Wn[NOFF * 16384];
// split-K partials
__device__ float g_part[NGRP * OUTN];

// ---------------------------------------------------------------------------
// Helpers
// ---------------------------------------------------------------------------
#define MBAR_INIT(a, c) \
    asm volatile("mbarrier.init.shared.b64 [%0], %1;" :: "r"(a), "r"(c) : "memory")
#define MBAR_EXPECT_TX(a, b) \
    asm volatile("mbarrier.arrive.expect_tx.shared.b64 _, [%0], %1;" :: "r"(a), "r"(b) : "memory")
#define BULK_G2S(dst, src, bytes, mbar) \
    asm volatile("cp.async.bulk.shared::cluster.global.mbarrier::complete_tx::bytes [%0], [%1], %2, [%3];" \
                 :: "r"(dst), "l"(src), "r"(bytes), "r"(mbar) : "memory")

__device__ __forceinline__ void mbar_wait_parity(uint32_t mbar, uint32_t parity) {
    asm volatile(
        "{\n\t.reg .pred P;\n\t"
        "WL_%=:\n\t"
        "mbarrier.try_wait.parity.acquire.cta.shared::cta.b64 P, [%0], %1, 0x989680;\n\t"
        "@!P bra WL_%=;\n\t}"
        :: "r"(mbar), "r"(parity) : "memory");
}

__device__ __forceinline__ uint32_t smem_u32(const void* p) {
    uint32_t a;
    asm("{ .reg .u64 t; cvta.to.shared.u64 t, %1; cvt.u32.u64 %0, t; }" : "=r"(a) : "l"(p));
    return a;
}

__device__ __forceinline__ void ldsm_x4(uint32_t* r, uint32_t addr) {
    asm volatile("ldmatrix.sync.aligned.m8n8.x4.shared.b16 {%0,%1,%2,%3}, [%4];"
                 : "=r"(r[0]), "=r"(r[1]), "=r"(r[2]), "=r"(r[3]) : "r"(addr));
}

__device__ __forceinline__ void mma_f16(float* c, const uint32_t* a, uint32_t b0, uint32_t b1) {
    asm volatile(
        "mma.sync.aligned.m16n8k16.row.col.f32.f16.f16.f32 "
        "{%0,%1,%2,%3}, {%4,%5,%6,%7}, {%8,%9}, {%0,%1,%2,%3};"
        : "+f"(c[0]), "+f"(c[1]), "+f"(c[2]), "+f"(c[3])
        : "r"(a[0]), "r"(a[1]), "r"(a[2]), "r"(a[3]), "r"(b0), "r"(b1));
}

__device__ __forceinline__ uint32_t pack_h(float f0, float f1) {
    __half h0 = __float2half(f0), h1 = __float2half(f1);
    return ((uint32_t)__half_as_ushort(h1) << 16) | __half_as_ushort(h0);
}

// ---------------------------------------------------------------------------
// Kernel 1: zero aggF + pack W (fp16, SW128 pre-swizzled)
// ---------------------------------------------------------------------------
__global__ void prep_kernel(const float* __restrict__ weight) {
    int bid = blockIdx.x;
    if (bid < 216) {
        int t = bid * 256 + threadIdx.x;
        ((float4*)g_aggF)[t] = make_float4(0.f, 0.f, 0.f, 0.f);
    } else {
        int i = (bid - 216) * 256 + threadIdx.x;   // 0..110591
        int n  = i & 127;
        int k2 = (i >> 7) & 31;
        int o  = i >> 12;                          // 0..26
        float w0 = weight[(o * CIN + 2 * k2) * COUT + n];
        float w1 = weight[(o * CIN + 2 * k2 + 1) * COUT + n];
        // SW128 swizzle: chunk bits[6:4] ^= (n&7)
        uint32_t off = (uint32_t)n * 128 + (((uint32_t)k2 * 4) ^ (((uint32_t)n & 7) << 4));
        *(uint32_t*)(g_Wn + (size_t)o * 16384 + off) = pack_h(w0, w1);
    }
}

// ---------------------------------------------------------------------------
// Kernel 2: scatter-add features into per-voxel bins
// ---------------------------------------------------------------------------
__global__ void aggregate_kernel(const float* __restrict__ points,
                                 const float* __restrict__ feats) {
    int gid = blockIdx.x * blockDim.x + threadIdx.x;
    if (gid >= BATCH * NPTS * CIN) return;
    int c = gid & (CIN - 1);
    int p = gid >> 6;
    int b = p / NPTS;
    int vx = (int)points[p * 3 + 0];
    int vy = (int)points[p * 3 + 1];
    int vz = (int)points[p * 3 + 2];
    if ((unsigned)vx >= GRIDV || (unsigned)vy >= GRIDV || (unsigned)vz >= GRIDV) return;
    int lin = (vx * GRIDV + vy) * GRIDV + vz;
    atomicAdd(&g_aggF[(b * NVOX + lin) * CIN + c], feats[gid]);
}

// ---------------------------------------------------------------------------
// Kernel 3: convert aggF -> fp16 rows (once per voxel), plus zero row
// ---------------------------------------------------------------------------
__global__ void convert_kernel() {
    int gid = blockIdx.x * blockDim.x + threadIdx.x;
    if (gid >= (NROWS + 1) * 32) return;
    int row = gid >> 5;
    int c2  = gid & 31;
    uint32_t hp = 0;
    if (row < NROWS) {
        float2 v = *(const float2*)(g_aggF + (size_t)row * CIN + c2 * 2);
        hp = pack_h(v.x, v.y);
    }
    *(uint32_t*)(g_aggH + (size_t)row * 128 + c2 * 4) = hp;
}

// ---------------------------------------------------------------------------
// Kernel 4: fp16 1-pass mma conv. A fragments loaded DIRECTLY from gmem into
// registers (16 LDG.32/thread/offset, prefetched 1 offset ahead); W via
// cp.async.bulk 3-stage ring. grid = NTILE*NGRP = 128 blocks, 256 thr.
// Warp (wm 0..3, wn 0..1): 16 rows x 64 couts. Partials to g_part[g].
// ---------------------------------------------------------------------------
#define NSTG   3
#define WBUF   16384                   // per-offset W (fp16, swizzled)
#define SMO_W  0
#define SMO_VOX (NSTG * WBUF)          // 49152
#define SMO_MBAR (SMO_VOX + 3 * TM * 4)  // 49920
#define SMEM_TOTAL (SMO_MBAR + 64)     // 49984

__global__ __launch_bounds__(256, 1)
void conv_mma_kernel(const float* __restrict__ points) {
    extern __shared__ __align__(1024) unsigned char smem[];
    int* svox = (int*)(smem + SMO_VOX);

    const int tid  = threadIdx.x;
    const int warp = tid >> 5;
    const int lane = tid & 31;
    const int wm   = warp >> 1;      // 0..3 : rows [wm*16, +16)
    const int wn   = warp & 1;       // 0..1 : couts [wn*64, +64)
    const int grp  = lane >> 2;      // 0..7
    const int tig  = lane & 3;       // 0..3

    const int g    = blockIdx.x & 1;         // offset group
    const int tile = blockIdx.x >> 1;        // point tile
    const int o0   = g ? 14 : 0;
    const int OE   = g ? 13 : 14;            // offsets in this group
    const int p0   = tile * TM;
    const int b    = p0 >> 11;               // / NPTS

    if (tid < TM) {
        int p = p0 + tid;
        svox[tid]          = (int)points[p * 3 + 0];
        svox[TM + tid]     = (int)points[p * 3 + 1];
        svox[2 * TM + tid] = (int)points[p * 3 + 2];
    }
    __syncthreads();

    const uint32_t sb = smem_u32(smem);

    if (tid == 0) {
        MBAR_INIT(sb + SMO_MBAR,      1);
        MBAR_INIT(sb + SMO_MBAR + 8,  1);
        MBAR_INIT(sb + SMO_MBAR + 16, 1);
    }
    __syncthreads();

    // ---- this thread's two A rows (points wm*16+grp and +8) ----
    const int mA = wm * 16 + grp;
    const int vxA = svox[mA],     vyA = svox[TM + mA],     vzA = svox[2 * TM + mA];
    const int vxB = svox[mA + 8], vyB = svox[TM + mA + 8], vzB = svox[2 * TM + mA + 8];
    const int bNV = b * NVOX;

    // direct-gather A fragments for offset o into 16 regs
    auto prefetchA = [&](int o, uint32_t* a) {
        int dx = o / 9 - 1, dy = (o / 3) % 3 - 1, dz = o % 3 - 1;
        int nxA = vxA + dx, nyA = vyA + dy, nzA = vzA + dz;
        int nxB = vxB + dx, nyB = vyB + dy, nzB = vzB + dz;
        int rA = ((unsigned)nxA < GRIDV && (unsigned)nyA < GRIDV && (unsigned)nzA < GRIDV)
               ? bNV + (nxA * GRIDV + nyA) * GRIDV + nzA : ZROW;
        int rB = ((unsigned)nxB < GRIDV && (unsigned)nyB < GRIDV && (unsigned)nzB < GRIDV)
               ? bNV + (nxB * GRIDV + nyB) * GRIDV + nzB : ZROW;
        const unsigned char* baseA = g_aggH + (size_t)rA * 128 + tig * 4;
        const unsigned char* baseB = g_aggH + (size_t)rB * 128 + tig * 4;
        #pragma unroll
        for (int kk = 0; kk < 4; kk++) {
            a[kk*4+0] = *(const uint32_t*)(baseA + kk * 32);
            a[kk*4+1] = *(const uint32_t*)(baseB + kk * 32);
            a[kk*4+2] = *(const uint32_t*)(baseA + kk * 32 + 16);
            a[kk*4+3] = *(const uint32_t*)(baseB + kk * 32 + 16);
        }
    };
    auto issueW = [&](int o, int s) {
        if (tid == 0) {
            uint32_t mb = sb + SMO_MBAR + s * 8;
            MBAR_EXPECT_TX(mb, WBUF);
            BULK_G2S(sb + SMO_W + s * WBUF, g_Wn + (size_t)o * WBUF, WBUF, mb);
        }
    };

    float c[32];
    #pragma unroll
    for (int i = 0; i < 32; i++) c[i] = 0.f;

    // ---- prologue: W stages 0,1 + A for first offset ----
    issueW(o0, 0);
    issueW(o0 + 1, 1);
    uint32_t aCur[16], aNxt[16];
    prefetchA(o0, aCur);

    // ---- B ldmatrix lane addressing (128B rows, SW128) ----
    const int bc   = lane & 7;
    const uint32_t bXor = (uint32_t)bc << 4;
    const uint32_t bRow0 = sb + SMO_W
        + (uint32_t)(wn * 64 + ((lane >> 4) & 1) * 8 + bc) * 128;
    const uint32_t bKsel = ((lane >> 3) & 1) * 16;

    for (int i = 0; i < OE; i++) {
        const int s = i % 3;

        // W prefetch 2 ahead; A prefetch 1 ahead (registers)
        if (i + 2 < OE) issueW(o0 + i + 2, (i + 2) % 3);
        if (i + 1 < OE) prefetchA(o0 + i + 1, aNxt);

        // wait for this stage's W
        mbar_wait_parity(sb + SMO_MBAR + s * 8, (uint32_t)((i / 3) & 1));

        // ---- 1-pass mma over 4 k-steps (A in registers) ----
        const uint32_t bB = bRow0 + (uint32_t)s * WBUF;
        #pragma unroll
        for (int kk = 0; kk < 4; kk++) {
            const uint32_t kx = ((uint32_t)(kk * 32) + bKsel) ^ bXor;
            #pragma unroll
            for (int j = 0; j < 4; j++) {
                uint32_t bh[4];
                ldsm_x4(bh, bB + j * 2048 + kx);
                mma_f16(&c[(2 * j) * 4],     &aCur[kk * 4], bh[0], bh[1]);
                mma_f16(&c[(2 * j + 1) * 4], &aCur[kk * 4], bh[2], bh[3]);
            }
        }

        // rotate A registers
        #pragma unroll
        for (int q = 0; q < 16; q++) aCur[q] = aNxt[q];

        __syncthreads();   // stage-s smem reads done before its next producer
    }

    // ---- epilogue: vectorized partial write ----
    float* pout = g_part + (size_t)g * OUTN;
    const int r0 = p0 + wm * 16 + grp;
    #pragma unroll
    for (int f = 0; f < 8; f++) {
        int col = wn * 64 + f * 8 + tig * 2;
        const float* cc = &c[f * 4];
        *(float2*)(pout + (size_t)r0 * COUT + col)       = make_float2(cc[0], cc[1]);
        *(float2*)(pout + (size_t)(r0 + 8) * COUT + col) = make_float2(cc[2], cc[3]);
    }
}

// ---------------------------------------------------------------------------
// Kernel 5: reduce partials + bias -> out
// ---------------------------------------------------------------------------
__global__ void reduce_kernel(const float* __restrict__ bias, float* __restrict__ out) {
    int i = blockIdx.x * blockDim.x + threadIdx.x;   // float4 index, < OUTN/4
    if (i >= OUTN / 4) return;
    float4 a = ((const float4*)g_part)[i];
    float4 bq = ((const float4*)(g_part + OUTN))[i];
    float4 bv = ((const float4*)bias)[i & 31];
    float4 r;
    r.x = a.x + bq.x + bv.x;
    r.y = a.y + bq.y + bv.y;
    r.z = a.z + bq.z + bv.z;
    r.w = a.w + bq.w + bv.w;
    ((float4*)out)[i] = r;
}

// ---------------------------------------------------------------------------
extern "C" void kernel_launch(void* const* d_in, const int* in_sizes, int n_in,
                              void* d_out, int out_size) {
    const float* points  = (const float*)d_in[0];   // (B, N, 3)
    const float* feats   = (const float*)d_in[1];   // (B, N, CIN)
    const float* weight  = (const float*)d_in[2];   // (3,3,3,CIN,COUT)
    const float* bias    = (const float*)d_in[3];   // (COUT)
    float* out = (float*)d_out;                     // (B, N, COUT)

    cudaFuncSetAttribute(conv_mma_kernel,
                         cudaFuncAttributeMaxDynamicSharedMemorySize, SMEM_TOTAL);

    // 1) zero agg scratch + pack W (fp16 swizzled)
    prep_kernel<<<648, 256>>>(weight);
    // 2) per-voxel feature aggregation (fp32 atomics)
    aggregate_kernel<<<(BATCH * NPTS * CIN + 255) / 256, 256>>>(points, feats);
    // 3) convert aggF to fp16 rows (+ zero row)
    convert_kernel<<<((NROWS + 1) * 32 + 255) / 256, 256>>>();
    // 4) fp16 1-pass conv, register-direct A + bulk W -> partials
    conv_mma_kernel<<<NTILE * NGRP, 256, SMEM_TOTAL>>>(points);
    // 5) reduce partials + bias -> out
    reduce_kernel<<<(OUTN / 4 + 255) / 256, 256>>>(bias, out);
}

// round 14
// speedup vs baseline: 1.4058x; 1.1517x over previous
#include <cuda_runtime.h>
#include <cuda_fp16.h>
#include <cstdint>

// Problem constants
#define BATCH   2
#define NPTS    2048
#define CIN     64
#define COUT    128
#define GRIDV   12
#define NVOX    (GRIDV*GRIDV*GRIDV)   // 1728
#define NOFF    27
#define NGRP    4                     // offset groups: 7/7/7/6
#define TM      64                    // points per conv block
#define NTILE   (BATCH*NPTS/TM)       // 64 point tiles
#define NROWS   (BATCH*NVOX)          // 3456
#define ZROW    NROWS                 // dedicated zero row index
#define OUTN    (BATCH*NPTS*COUT)     // 524288

// Scratch (device globals; no allocation allowed)
__device__ __align__(16) unsigned char g_aggH[(NROWS + 1) * 128];  // fp16 agg rows (+zero row)
// W per offset: 16KB = [n][128B row], fp16, SW128-PRE-SWIZZLED
__device__ __align__(1024) unsigned char g_Wn[NOFF * 16384];
// split-K partials
__device__ float g_part[NGRP * OUTN];

// ---------------------------------------------------------------------------
// Helpers
// ---------------------------------------------------------------------------
#define MBAR_INIT(a, c) \
    asm volatile("mbarrier.init.shared.b64 [%0], %1;" :: "r"(a), "r"(c) : "memory")
#define MBAR_EXPECT_TX(a, b) \
    asm volatile("mbarrier.arrive.expect_tx.shared.b64 _, [%0], %1;" :: "r"(a), "r"(b) : "memory")
#define BULK_G2S(dst, src, bytes, mbar) \
    asm volatile("cp.async.bulk.shared::cluster.global.mbarrier::complete_tx::bytes [%0], [%1], %2, [%3];" \
                 :: "r"(dst), "l"(src), "r"(bytes), "r"(mbar) : "memory")

__device__ __forceinline__ void mbar_wait_parity(uint32_t mbar, uint32_t parity) {
    asm volatile(
        "{\n\t.reg .pred P;\n\t"
        "WL_%=:\n\t"
        "mbarrier.try_wait.parity.acquire.cta.shared::cta.b64 P, [%0], %1, 0x989680;\n\t"
        "@!P bra WL_%=;\n\t}"
        :: "r"(mbar), "r"(parity) : "memory");
}

__device__ __forceinline__ uint32_t smem_u32(const void* p) {
    uint32_t a;
    asm("{ .reg .u64 t; cvta.to.shared.u64 t, %1; cvt.u32.u64 %0, t; }" : "=r"(a) : "l"(p));
    return a;
}

__device__ __forceinline__ void ldsm_x4(uint32_t* r, uint32_t addr) {
    asm volatile("ldmatrix.sync.aligned.m8n8.x4.shared.b16 {%0,%1,%2,%3}, [%4];"
                 : "=r"(r[0]), "=r"(r[1]), "=r"(r[2]), "=r"(r[3]) : "r"(addr));
}

__device__ __forceinline__ void mma_f16(float* c, const uint32_t* a, uint32_t b0, uint32_t b1) {
    asm volatile(
        "mma.sync.aligned.m16n8k16.row.col.f32.f16.f16.f32 "
        "{%0,%1,%2,%3}, {%4,%5,%6,%7}, {%8,%9}, {%0,%1,%2,%3};"
        : "+f"(c[0]), "+f"(c[1]), "+f"(c[2]), "+f"(c[3])
        : "r"(a[0]), "r"(a[1]), "r"(a[2]), "r"(a[3]), "r"(b0), "r"(b1));
}

__device__ __forceinline__ uint32_t pack_h(float f0, float f1) {
    __half h0 = __float2half(f0), h1 = __float2half(f1);
    return ((uint32_t)__half_as_ushort(h1) << 16) | __half_as_ushort(h0);
}

// ---------------------------------------------------------------------------
// Kernel 1: zero aggH + pack W (fp16, SW128 pre-swizzled)
// blocks [0,109): zero g_aggH (27656 float4, guarded); [109,541): W pack
// ---------------------------------------------------------------------------
__global__ void prep_kernel(const float* __restrict__ weight) {
    int bid = blockIdx.x;
    if (bid < 109) {
        int t = bid * 256 + threadIdx.x;
        if (t < (NROWS + 1) * 128 / 16)
            ((float4*)g_aggH)[t] = make_float4(0.f, 0.f, 0.f, 0.f);
    } else {
        int i = (bid - 109) * 256 + threadIdx.x;   // 0..110591
        int n  = i & 127;
        int k2 = (i >> 7) & 31;
        int o  = i >> 12;                          // 0..26
        float w0 = weight[(o * CIN + 2 * k2) * COUT + n];
        float w1 = weight[(o * CIN + 2 * k2 + 1) * COUT + n];
        // SW128 swizzle: chunk bits[6:4] ^= (n&7)
        uint32_t off = (uint32_t)n * 128 + (((uint32_t)k2 * 4) ^ (((uint32_t)n & 7) << 4));
        *(uint32_t*)(g_Wn + (size_t)o * 16384 + off) = pack_h(w0, w1);
    }
}

// ---------------------------------------------------------------------------
// Kernel 2: scatter-add features directly into fp16 voxel bins (half2 atomics)
// one thread per (point, channel-pair): B*N*32 threads
// ---------------------------------------------------------------------------
__global__ void aggregate_kernel(const float* __restrict__ points,
                                 const float* __restrict__ feats) {
    int gid = blockIdx.x * blockDim.x + threadIdx.x;
    if (gid >= BATCH * NPTS * 32) return;
    int c2 = gid & 31;
    int p  = gid >> 5;
    int b  = p >> 11;                // / NPTS
    int vx = (int)points[p * 3 + 0];
    int vy = (int)points[p * 3 + 1];
    int vz = (int)points[p * 3 + 2];
    if ((unsigned)vx >= GRIDV || (unsigned)vy >= GRIDV || (unsigned)vz >= GRIDV) return;
    int row = b * NVOX + (vx * GRIDV + vy) * GRIDV + vz;
    float2 v = *(const float2*)(feats + (size_t)p * CIN + c2 * 2);
    __half2 hv = __floats2half2_rn(v.x, v.y);
    atomicAdd((__half2*)(g_aggH + (size_t)row * 128 + c2 * 4), hv);
}

// ---------------------------------------------------------------------------
// Kernel 3: fp16 1-pass mma conv. A fragments loaded directly from gmem into
// registers (16 LDG.32/thread/offset, prefetched 1 ahead); W via
// cp.async.bulk 3-stage ring. grid = NTILE*NGRP = 256 blocks, 2 CTA/SM.
// Warp (wm 0..3, wn 0..1): 16 rows x 64 couts. Partials to g_part[g].
// ---------------------------------------------------------------------------
#define NSTG   3
#define WBUF   16384                   // per-offset W (fp16, swizzled)
#define SMO_W  0
#define SMO_VOX (NSTG * WBUF)          // 49152
#define SMO_MBAR (SMO_VOX + 3 * TM * 4)  // 49920
#define SMEM_TOTAL (SMO_MBAR + 64)     // 49984

__global__ __launch_bounds__(256, 2)
void conv_mma_kernel(const float* __restrict__ points) {
    extern __shared__ __align__(1024) unsigned char smem[];
    int* svox = (int*)(smem + SMO_VOX);

    const int tid  = threadIdx.x;
    const int warp = tid >> 5;
    const int lane = tid & 31;
    const int wm   = warp >> 1;      // 0..3 : rows [wm*16, +16)
    const int wn   = warp & 1;       // 0..1 : couts [wn*64, +64)
    const int grp  = lane >> 2;      // 0..7
    const int tig  = lane & 3;       // 0..3

    const int g    = blockIdx.x & 3;         // offset group
    const int tile = blockIdx.x >> 2;        // point tile
    const int o0   = g * 7;
    const int OE   = (g == 3) ? 6 : 7;       // offsets in this group
    const int p0   = tile * TM;
    const int b    = p0 >> 11;               // / NPTS

    if (tid < TM) {
        int p = p0 + tid;
        svox[tid]          = (int)points[p * 3 + 0];
        svox[TM + tid]     = (int)points[p * 3 + 1];
        svox[2 * TM + tid] = (int)points[p * 3 + 2];
    }
    __syncthreads();

    const uint32_t sb = smem_u32(smem);

    if (tid == 0) {
        MBAR_INIT(sb + SMO_MBAR,      1);
        MBAR_INIT(sb + SMO_MBAR + 8,  1);
        MBAR_INIT(sb + SMO_MBAR + 16, 1);
    }
    __syncthreads();

    // ---- this thread's two A rows (points wm*16+grp and +8) ----
    const int mA = wm * 16 + grp;
    const int vxA = svox[mA],     vyA = svox[TM + mA],     vzA = svox[2 * TM + mA];
    const int vxB = svox[mA + 8], vyB = svox[TM + mA + 8], vzB = svox[2 * TM + mA + 8];
    const int bNV = b * NVOX;

    // direct-gather A fragments for offset o into 16 regs
    auto prefetchA = [&](int o, uint32_t* a) {
        int dx = o / 9 - 1, dy = (o / 3) % 3 - 1, dz = o % 3 - 1;
        int nxA = vxA + dx, nyA = vyA + dy, nzA = vzA + dz;
        int nxB = vxB + dx, nyB = vyB + dy, nzB = vzB + dz;
        int rA = ((unsigned)nxA < GRIDV && (unsigned)nyA < GRIDV && (unsigned)nzA < GRIDV)
               ? bNV + (nxA * GRIDV + nyA) * GRIDV + nzA : ZROW;
        int rB = ((unsigned)nxB < GRIDV && (unsigned)nyB < GRIDV && (unsigned)nzB < GRIDV)
               ? bNV + (nxB * GRIDV + nyB) * GRIDV + nzB : ZROW;
        const unsigned char* baseA = g_aggH + (size_t)rA * 128 + tig * 4;
        const unsigned char* baseB = g_aggH + (size_t)rB * 128 + tig * 4;
        #pragma unroll
        for (int kk = 0; kk < 4; kk++) {
            a[kk*4+0] = *(const uint32_t*)(baseA + kk * 32);
            a[kk*4+1] = *(const uint32_t*)(baseB + kk * 32);
            a[kk*4+2] = *(const uint32_t*)(baseA + kk * 32 + 16);
            a[kk*4+3] = *(const uint32_t*)(baseB + kk * 32 + 16);
        }
    };
    auto issueW = [&](int o, int s) {
        if (tid == 0) {
            uint32_t mb = sb + SMO_MBAR + s * 8;
            MBAR_EXPECT_TX(mb, WBUF);
            BULK_G2S(sb + SMO_W + s * WBUF, g_Wn + (size_t)o * WBUF, WBUF, mb);
        }
    };

    float c[32];
    #pragma unroll
    for (int i = 0; i < 32; i++) c[i] = 0.f;

    // ---- prologue: W stages 0,1 + A for first offset ----
    issueW(o0, 0);
    issueW(o0 + 1, 1);
    uint32_t aCur[16], aNxt[16];
    prefetchA(o0, aCur);

    // ---- B ldmatrix lane addressing (128B rows, SW128) ----
    const int bc   = lane & 7;
    const uint32_t bXor = (uint32_t)bc << 4;
    const uint32_t bRow0 = sb + SMO_W
        + (uint32_t)(wn * 64 + ((lane >> 4) & 1) * 8 + bc) * 128;
    const uint32_t bKsel = ((lane >> 3) & 1) * 16;

    for (int i = 0; i < OE; i++) {
        const int s = i % 3;

        // W prefetch 2 ahead; A prefetch 1 ahead (registers)
        if (i + 2 < OE) issueW(o0 + i + 2, (i + 2) % 3);
        if (i + 1 < OE) prefetchA(o0 + i + 1, aNxt);

        // wait for this stage's W
        mbar_wait_parity(sb + SMO_MBAR + s * 8, (uint32_t)((i / 3) & 1));

        // ---- 1-pass mma over 4 k-steps (A in registers) ----
        const uint32_t bB = bRow0 + (uint32_t)s * WBUF;
        #pragma unroll
        for (int kk = 0; kk < 4; kk++) {
            const uint32_t kx = ((uint32_t)(kk * 32) + bKsel) ^ bXor;
            #pragma unroll
            for (int j = 0; j < 4; j++) {
                uint32_t bh[4];
                ldsm_x4(bh, bB + j * 2048 + kx);
                mma_f16(&c[(2 * j) * 4],     &aCur[kk * 4], bh[0], bh[1]);
                mma_f16(&c[(2 * j + 1) * 4], &aCur[kk * 4], bh[2], bh[3]);
            }
        }

        // rotate A registers
        #pragma unroll
        for (int q = 0; q < 16; q++) aCur[q] = aNxt[q];

        __syncthreads();   // stage-s smem reads done before its next producer
    }

    // ---- epilogue: vectorized partial write ----
    float* pout = g_part + (size_t)g * OUTN;
    const int r0 = p0 + wm * 16 + grp;
    #pragma unroll
    for (int f = 0; f < 8; f++) {
        int col = wn * 64 + f * 8 + tig * 2;
        const float* cc = &c[f * 4];
        *(float2*)(pout + (size_t)r0 * COUT + col)       = make_float2(cc[0], cc[1]);
        *(float2*)(pout + (size_t)(r0 + 8) * COUT + col) = make_float2(cc[2], cc[3]);
    }
}

// ---------------------------------------------------------------------------
// Kernel 4: reduce partials + bias -> out
// ---------------------------------------------------------------------------
__global__ void reduce_kernel(const float* __restrict__ bias, float* __restrict__ out) {
    int i = blockIdx.x * blockDim.x + threadIdx.x;   // float4 index, < OUTN/4
    if (i >= OUTN / 4) return;
    float4 bv = ((const float4*)bias)[i & 31];
    float4 r = bv;
    #pragma unroll
    for (int g = 0; g < NGRP; g++) {
        float4 v = ((const float4*)(g_part + (size_t)g * OUTN))[i];
        r.x += v.x; r.y += v.y; r.z += v.z; r.w += v.w;
    }
    ((float4*)out)[i] = r;
}

// ---------------------------------------------------------------------------
extern "C" void kernel_launch(void* const* d_in, const int* in_sizes, int n_in,
                              void* d_out, int out_size) {
    const float* points  = (const float*)d_in[0];   // (B, N, 3)
    const float* feats   = (const float*)d_in[1];   // (B, N, CIN)
    const float* weight  = (const float*)d_in[2];   // (3,3,3,CIN,COUT)
    const float* bias    = (const float*)d_in[3];   // (COUT)
    float* out = (float*)d_out;                     // (B, N, COUT)

    cudaFuncSetAttribute(conv_mma_kernel,
                         cudaFuncAttributeMaxDynamicSharedMemorySize, SMEM_TOTAL);

    // 1) zero fp16 agg rows + pack W (fp16 swizzled)
    prep_kernel<<<541, 256>>>(weight);
    // 2) per-voxel fp16 aggregation (half2 atomics)
    aggregate_kernel<<<(BATCH * NPTS * 32 + 255) / 256, 256>>>(points, feats);
    // 3) fp16 1-pass conv, register-direct A + bulk W -> partials (2 CTA/SM)
    conv_mma_kernel<<<NTILE * NGRP, 256, SMEM_TOTAL>>>(points);
    // 4) reduce partials + bias -> out
    reduce_kernel<<<(OUTN / 4 + 255) / 256, 256>>>(bias, out);
}

// round 15
// speedup vs baseline: 1.5444x; 1.0986x over previous
#include <cuda_runtime.h>
#include <cuda_fp16.h>
#include <cstdint>

// Problem constants
#define BATCH   2
#define NPTS    2048
#define CIN     64
#define COUT    128
#define GRIDV   12
#define NVOX    (GRIDV*GRIDV*GRIDV)   // 1728
#define NOFF    27
#define NGRP    4                     // offset groups: 7/7/7/6
#define TM      64                    // points per conv block
#define NTILE   (BATCH*NPTS/TM)       // 64 point tiles
#define NROWS   (BATCH*NVOX)          // 3456
#define ZROW    NROWS                 // dedicated zero row index
#define OUTN    (BATCH*NPTS*COUT)     // 524288

// Scratch (device globals; no allocation allowed)
__device__ __align__(16) unsigned char g_aggH[(NROWS + 1) * 128];  // fp16 agg rows (+zero row)
// W per offset: 16KB = [n][128B row], fp16, SW128-PRE-SWIZZLED
__device__ __align__(1024) unsigned char g_Wn[NOFF * 16384];

// ---------------------------------------------------------------------------
// Helpers
// ---------------------------------------------------------------------------
#define MBAR_INIT(a, c) \
    asm volatile("mbarrier.init.shared.b64 [%0], %1;" :: "r"(a), "r"(c) : "memory")
#define MBAR_EXPECT_TX(a, b) \
    asm volatile("mbarrier.arrive.expect_tx.shared.b64 _, [%0], %1;" :: "r"(a), "r"(b) : "memory")
#define BULK_G2S(dst, src, bytes, mbar) \
    asm volatile("cp.async.bulk.shared::cluster.global.mbarrier::complete_tx::bytes [%0], [%1], %2, [%3];" \
                 :: "r"(dst), "l"(src), "r"(bytes), "r"(mbar) : "memory")
#define RED_ADD_V2(addr, x, y) \
    asm volatile("red.global.add.v2.f32 [%0], {%1, %2};" :: "l"(addr), "f"(x), "f"(y) : "memory")

__device__ __forceinline__ void mbar_wait_parity(uint32_t mbar, uint32_t parity) {
    asm volatile(
        "{\n\t.reg .pred P;\n\t"
        "WL_%=:\n\t"
        "mbarrier.try_wait.parity.acquire.cta.shared::cta.b64 P, [%0], %1, 0x989680;\n\t"
        "@!P bra WL_%=;\n\t}"
        :: "r"(mbar), "r"(parity) : "memory");
}

__device__ __forceinline__ uint32_t smem_u32(const void* p) {
    uint32_t a;
    asm("{ .reg .u64 t; cvta.to.shared.u64 t, %1; cvt.u32.u64 %0, t; }" : "=r"(a) : "l"(p));
    return a;
}

__device__ __forceinline__ void ldsm_x4(uint32_t* r, uint32_t addr) {
    asm volatile("ldmatrix.sync.aligned.m8n8.x4.shared.b16 {%0,%1,%2,%3}, [%4];"
                 : "=r"(r[0]), "=r"(r[1]), "=r"(r[2]), "=r"(r[3]) : "r"(addr));
}

__device__ __forceinline__ void mma_f16(float* c, const uint32_t* a, uint32_t b0, uint32_t b1) {
    asm volatile(
        "mma.sync.aligned.m16n8k16.row.col.f32.f16.f16.f32 "
        "{%0,%1,%2,%3}, {%4,%5,%6,%7}, {%8,%9}, {%0,%1,%2,%3};"
        : "+f"(c[0]), "+f"(c[1]), "+f"(c[2]), "+f"(c[3])
        : "r"(a[0]), "r"(a[1]), "r"(a[2]), "r"(a[3]), "r"(b0), "r"(b1));
}

__device__ __forceinline__ uint32_t pack_h(float f0, float f1) {
    __half h0 = __float2half(f0), h1 = __float2half(f1);
    return ((uint32_t)__half_as_ushort(h1) << 16) | __half_as_ushort(h0);
}

// ---------------------------------------------------------------------------
// Kernel 1: zero aggH + pack W (fp16, SW128 pre-swizzled) + out = bias
// blocks [0,109): zero g_aggH; [109,541): W pack; [541,1053): bias init
// ---------------------------------------------------------------------------
__global__ void prep_kernel(const float* __restrict__ weight,
                            const float* __restrict__ bias,
                            float* __restrict__ out) {
    int bid = blockIdx.x;
    if (bid < 109) {
        int t = bid * 256 + threadIdx.x;
        if (t < (NROWS + 1) * 128 / 16)
            ((float4*)g_aggH)[t] = make_float4(0.f, 0.f, 0.f, 0.f);
    } else if (bid < 541) {
        int i = (bid - 109) * 256 + threadIdx.x;   // 0..110591
        int n  = i & 127;
        int k2 = (i >> 7) & 31;
        int o  = i >> 12;                          // 0..26
        float w0 = weight[(o * CIN + 2 * k2) * COUT + n];
        float w1 = weight[(o * CIN + 2 * k2 + 1) * COUT + n];
        // SW128 swizzle: chunk bits[6:4] ^= (n&7)
        uint32_t off = (uint32_t)n * 128 + (((uint32_t)k2 * 4) ^ (((uint32_t)n & 7) << 4));
        *(uint32_t*)(g_Wn + (size_t)o * 16384 + off) = pack_h(w0, w1);
    } else {
        int i = (bid - 541) * 256 + threadIdx.x;   // float4 idx < OUTN/4 = 131072
        ((float4*)out)[i] = ((const float4*)bias)[i & 31];
    }
}

// ---------------------------------------------------------------------------
// Kernel 2: scatter-add features directly into fp16 voxel bins (half2 atomics)
// ---------------------------------------------------------------------------
__global__ void aggregate_kernel(const float* __restrict__ points,
                                 const float* __restrict__ feats) {
    int gid = blockIdx.x * blockDim.x + threadIdx.x;
    if (gid >= BATCH * NPTS * 32) return;
    int c2 = gid & 31;
    int p  = gid >> 5;
    int b  = p >> 11;                // / NPTS
    int vx = (int)points[p * 3 + 0];
    int vy = (int)points[p * 3 + 1];
    int vz = (int)points[p * 3 + 2];
    if ((unsigned)vx >= GRIDV || (unsigned)vy >= GRIDV || (unsigned)vz >= GRIDV) return;
    int row = b * NVOX + (vx * GRIDV + vy) * GRIDV + vz;
    float2 v = *(const float2*)(feats + (size_t)p * CIN + c2 * 2);
    __half2 hv = __floats2half2_rn(v.x, v.y);
    atomicAdd((__half2*)(g_aggH + (size_t)row * 128 + c2 * 4), hv);
}

// ---------------------------------------------------------------------------
// Kernel 3: fp16 1-pass mma conv. A fragments register-direct from gmem
// (prefetched 1 ahead); W via cp.async.bulk 3-stage ring.
// grid = NTILE*NGRP = 256 blocks, 2 CTA/SM. Warp (wm 0..3, wn 0..1).
// Epilogue: red.global.add.v2.f32 into bias-initialized out (no reduce pass).
// ---------------------------------------------------------------------------
#define NSTG   3
#define WBUF   16384                   // per-offset W (fp16, swizzled)
#define SMO_W  0
#define SMO_VOX (NSTG * WBUF)          // 49152
#define SMO_MBAR (SMO_VOX + 3 * TM * 4)  // 49920
#define SMEM_TOTAL (SMO_MBAR + 64)     // 49984

__global__ __launch_bounds__(256, 2)
void conv_mma_kernel(const float* __restrict__ points, float* __restrict__ out) {
    extern __shared__ __align__(1024) unsigned char smem[];
    int* svox = (int*)(smem + SMO_VOX);

    const int tid  = threadIdx.x;
    const int warp = tid >> 5;
    const int lane = tid & 31;
    const int wm   = warp >> 1;      // 0..3 : rows [wm*16, +16)
    const int wn   = warp & 1;       // 0..1 : couts [wn*64, +64)
    const int grp  = lane >> 2;      // 0..7
    const int tig  = lane & 3;       // 0..3

    const int g    = blockIdx.x & 3;         // offset group
    const int tile = blockIdx.x >> 2;        // point tile
    const int o0   = g * 7;
    const int OE   = (g == 3) ? 6 : 7;       // offsets in this group
    const int p0   = tile * TM;
    const int b    = p0 >> 11;               // / NPTS

    if (tid < TM) {
        int p = p0 + tid;
        svox[tid]          = (int)points[p * 3 + 0];
        svox[TM + tid]     = (int)points[p * 3 + 1];
        svox[2 * TM + tid] = (int)points[p * 3 + 2];
    }
    __syncthreads();

    const uint32_t sb = smem_u32(smem);

    if (tid == 0) {
        MBAR_INIT(sb + SMO_MBAR,      1);
        MBAR_INIT(sb + SMO_MBAR + 8,  1);
        MBAR_INIT(sb + SMO_MBAR + 16, 1);
    }
    __syncthreads();

    // ---- this thread's two A rows (points wm*16+grp and +8) ----
    const int mA = wm * 16 + grp;
    const int vxA = svox[mA],     vyA = svox[TM + mA],     vzA = svox[2 * TM + mA];
    const int vxB = svox[mA + 8], vyB = svox[TM + mA + 8], vzB = svox[2 * TM + mA + 8];
    const int bNV = b * NVOX;

    // direct-gather A fragments for offset o into 16 regs
    auto prefetchA = [&](int o, uint32_t* a) {
        int dx = o / 9 - 1, dy = (o / 3) % 3 - 1, dz = o % 3 - 1;
        int nxA = vxA + dx, nyA = vyA + dy, nzA = vzA + dz;
        int nxB = vxB + dx, nyB = vyB + dy, nzB = vzB + dz;
        int rA = ((unsigned)nxA < GRIDV && (unsigned)nyA < GRIDV && (unsigned)nzA < GRIDV)
               ? bNV + (nxA * GRIDV + nyA) * GRIDV + nzA : ZROW;
        int rB = ((unsigned)nxB < GRIDV && (unsigned)nyB < GRIDV && (unsigned)nzB < GRIDV)
               ? bNV + (nxB * GRIDV + nyB) * GRIDV + nzB : ZROW;
        const unsigned char* baseA = g_aggH + (size_t)rA * 128 + tig * 4;
        const unsigned char* baseB = g_aggH + (size_t)rB * 128 + tig * 4;
        #pragma unroll
        for (int kk = 0; kk < 4; kk++) {
            a[kk*4+0] = *(const uint32_t*)(baseA + kk * 32);
            a[kk*4+1] = *(const uint32_t*)(baseB + kk * 32);
            a[kk*4+2] = *(const uint32_t*)(baseA + kk * 32 + 16);
            a[kk*4+3] = *(const uint32_t*)(baseB + kk * 32 + 16);
        }
    };
    auto issueW = [&](int o, int s) {
        if (tid == 0) {
            uint32_t mb = sb + SMO_MBAR + s * 8;
            MBAR_EXPECT_TX(mb, WBUF);
            BULK_G2S(sb + SMO_W + s * WBUF, g_Wn + (size_t)o * WBUF, WBUF, mb);
        }
    };

    float c[32];
    #pragma unroll
    for (int i = 0; i < 32; i++) c[i] = 0.f;

    // ---- prologue: W stages 0,1 + A for first offset ----
    issueW(o0, 0);
    issueW(o0 + 1, 1);
    uint32_t aCur[16], aNxt[16];
    prefetchA(o0, aCur);

    // ---- B ldmatrix lane addressing (128B rows, SW128) ----
    const int bc   = lane & 7;
    const uint32_t bXor = (uint32_t)bc << 4;
    const uint32_t bRow0 = sb + SMO_W
        + (uint32_t)(wn * 64 + ((lane >> 4) & 1) * 8 + bc) * 128;
    const uint32_t bKsel = ((lane >> 3) & 1) * 16;

    for (int i = 0; i < OE; i++) {
        const int s = i % 3;

        // W prefetch 2 ahead; A prefetch 1 ahead (registers)
        if (i + 2 < OE) issueW(o0 + i + 2, (i + 2) % 3);
        if (i + 1 < OE) prefetchA(o0 + i + 1, aNxt);

        // wait for this stage's W
        mbar_wait_parity(sb + SMO_MBAR + s * 8, (uint32_t)((i / 3) & 1));

        // ---- 1-pass mma over 4 k-steps (A in registers) ----
        const uint32_t bB = bRow0 + (uint32_t)s * WBUF;
        #pragma unroll
        for (int kk = 0; kk < 4; kk++) {
            const uint32_t kx = ((uint32_t)(kk * 32) + bKsel) ^ bXor;
            #pragma unroll
            for (int j = 0; j < 4; j++) {
                uint32_t bh[4];
                ldsm_x4(bh, bB + j * 2048 + kx);
                mma_f16(&c[(2 * j) * 4],     &aCur[kk * 4], bh[0], bh[1]);
                mma_f16(&c[(2 * j + 1) * 4], &aCur[kk * 4], bh[2], bh[3]);
            }
        }

        // rotate A registers
        #pragma unroll
        for (int q = 0; q < 16; q++) aCur[q] = aNxt[q];

        __syncthreads();   // stage-s smem reads done before its next producer
    }

    // ---- epilogue: vector float2 reductions into bias-initialized out ----
    const int r0 = p0 + wm * 16 + grp;
    #pragma unroll
    for (int f = 0; f < 8; f++) {
        int col = wn * 64 + f * 8 + tig * 2;
        const float* cc = &c[f * 4];
        float* oA = out + (size_t)r0 * COUT + col;
        float* oB = out + (size_t)(r0 + 8) * COUT + col;
        RED_ADD_V2(oA, cc[0], cc[1]);
        RED_ADD_V2(oB, cc[2], cc[3]);
    }
}

// ---------------------------------------------------------------------------
extern "C" void kernel_launch(void* const* d_in, const int* in_sizes, int n_in,
                              void* d_out, int out_size) {
    const float* points  = (const float*)d_in[0];   // (B, N, 3)
    const float* feats   = (const float*)d_in[1];   // (B, N, CIN)
    const float* weight  = (const float*)d_in[2];   // (3,3,3,CIN,COUT)
    const float* bias    = (const float*)d_in[3];   // (COUT)
    float* out = (float*)d_out;                     // (B, N, COUT)

    cudaFuncSetAttribute(conv_mma_kernel,
                         cudaFuncAttributeMaxDynamicSharedMemorySize, SMEM_TOTAL);

    // 1) zero fp16 agg rows + pack W (fp16 swizzled) + out = bias
    prep_kernel<<<1053, 256>>>(weight, bias, out);
    // 2) per-voxel fp16 aggregation (half2 atomics)
    aggregate_kernel<<<(BATCH * NPTS * 32 + 255) / 256, 256>>>(points, feats);
    // 3) fp16 1-pass conv, register-direct A + bulk W, red.v2 epilogue
    conv_mma_kernel<<<NTILE * NGRP, 256, SMEM_TOTAL>>>(points, out);
}